// round 2
// baseline (speedup 1.0000x reference)
#include <cuda_runtime.h>
#include <cstdint>

// SphericalVectorPool: B=1, N=2048, A=2048, S=16 scales, out [A, 4*S] f32.
//
// R2 changes vs R1 (30.0us):
//  - svp_main: packed fma.rn.f32x2 accumulation (accs as {fi,gx} / {gy,gz}
//    pairs) -> fma-pipe ops/pair 91 -> 59; MUFU (17 ops x rt8) now binding.
//  - svp_reduce: float4 loads across `a` (32 x LDG.128 per thread, MLP 4x)
//    to fix the latency-bound 2.3TB/s reduce.

namespace {
constexpr int A_TOTAL = 2048;
constexpr int N_TOTAL = 2048;
constexpr int S       = 16;
constexpr int NCH     = 4 * S;              // 64 output channels
constexpr int NSPLIT  = 32;                 // N-dimension partitions
constexpr int CHUNK   = N_TOTAL / NSPLIT;   // 64 input points per CTA
constexpr int BLOCK   = 128;
constexpr float LOG2E = 1.4426950408889634f;
}

// 32 * 64 * 2048 * 4B = 16 MB scratch for partial sums.
__device__ float g_partial[NSPLIT][NCH][A_TOTAL];

__device__ __forceinline__ float ex2f(float x) {
    float y;
    asm("ex2.approx.ftz.f32 %0, %1;" : "=f"(y) : "f"(x));
    return y;
}

__device__ __forceinline__ uint64_t pack2(float lo, float hi) {
    uint64_t v;
    asm("mov.b64 %0, {%1, %2};" : "=l"(v) : "f"(lo), "f"(hi));
    return v;
}

__device__ __forceinline__ void unpack2(float& lo, float& hi, uint64_t v) {
    asm("mov.b64 {%0, %1}, %2;" : "=f"(lo), "=f"(hi) : "l"(v));
}

// d = a * b + d  (packed f32x2)
__device__ __forceinline__ void fma2(uint64_t& d, uint64_t a, uint64_t b) {
    asm("fma.rn.f32x2 %0, %1, %2, %0;" : "+l"(d) : "l"(a), "l"(b));
}

__global__ __launch_bounds__(BLOCK, 4) void svp_main(
    const float* __restrict__ f,
    const float* __restrict__ coords,
    const float* __restrict__ out_coords,
    const float* __restrict__ mu)
{
    __shared__ float4 tile[CHUNK];

    const int a  = blockIdx.x * BLOCK + threadIdx.x;
    const int n0 = blockIdx.y * CHUNK;

    // Stage this CTA's chunk of input points into smem as (x, y, z, f).
    for (int j = threadIdx.x; j < CHUNK; j += BLOCK) {
        const int n = n0 + j;
        tile[j] = make_float4(coords[3 * n + 0], coords[3 * n + 1],
                              coords[3 * n + 2], f[n]);
    }

    // Per-scale exp2 argument factors: -log2(e) * mu_s, kept in registers.
    float nmu[S];
    #pragma unroll
    for (int s = 0; s < S; ++s) nmu[s] = -LOG2E * mu[s];

    const float Rx = out_coords[3 * a + 0];
    const float Ry = out_coords[3 * a + 1];
    const float Rz = out_coords[3 * a + 2];

    // accA[s] = {sum e*fi, sum e*gx}; accB[s] = {sum e*gy, sum e*gz}
    uint64_t accA[S], accB[S];
    #pragma unroll
    for (int s = 0; s < S; ++s) { accA[s] = 0ull; accB[s] = 0ull; }

    __syncthreads();

    for (int j = 0; j < CHUNK; ++j) {
        const float4 p = tile[j];                 // broadcast LDS.128
        const float dx = p.x - Rx;
        const float dy = p.y - Ry;
        const float dz = p.z - Rz;
        const float r2   = fmaf(dx, dx, fmaf(dy, dy, dz * dz));
        const float rinv = rsqrtf(r2);            // MUFU.RSQ
        const float r    = r2 * rinv;
        const float fi   = p.w;
        const float g    = fi * rinv;

        const uint64_t fgx = pack2(fi, g * dx);   // {fi, gx}
        const uint64_t gyz = pack2(g * dy, g * dz);

        #pragma unroll
        for (int s = 0; s < S; ++s) {
            const float e = ex2f(r * nmu[s]);     // exp(-mu_s * r)
            const uint64_t e2 = pack2(e, e);
            fma2(accA[s], e2, fgx);               // l=0 and l=1,x
            fma2(accB[s], e2, gyz);               // l=1,y and l=1,z
        }
    }

    // Coalesced partial stores: channel-major, a contiguous.
    const int y = blockIdx.y;
    #pragma unroll
    for (int s = 0; s < S; ++s) {
        float v0, v1x, v1y, v1z;
        unpack2(v0, v1x, accA[s]);
        unpack2(v1y, v1z, accB[s]);
        g_partial[y][s][a]             = v0;
        g_partial[y][S + 3 * s + 0][a] = v1x;
        g_partial[y][S + 3 * s + 1][a] = v1y;
        g_partial[y][S + 3 * s + 2][a] = v1z;
    }
}

// Each thread reduces one channel c over 4 consecutive `a` (float4 loads).
__global__ void svp_reduce(
    float* __restrict__ out,
    const float* __restrict__ r_norms,
    const float* __restrict__ an0,
    const float* __restrict__ an1)
{
    const int idx = blockIdx.x * blockDim.x + threadIdx.x;  // 64 * 512
    const int c  = idx >> 9;          // channel
    const int g  = idx & 511;         // a-group
    const int a0 = g * 4;

    float4 acc = make_float4(0.f, 0.f, 0.f, 0.f);
    #pragma unroll
    for (int y = 0; y < NSPLIT; ++y) {
        const float4 v =
            *reinterpret_cast<const float4*>(&g_partial[y][c][a0]);
        acc.x += v.x; acc.y += v.y; acc.z += v.z; acc.w += v.w;
    }

    float scale;
    if (c < S) {
        scale = r_norms[c] * an0[0];
    } else {
        const int c2 = c - S;
        const int s  = c2 / 3;
        const int d  = c2 - 3 * s;
        scale = r_norms[s] * an1[d];
    }

    out[(a0 + 0) * NCH + c] = acc.x * scale;
    out[(a0 + 1) * NCH + c] = acc.y * scale;
    out[(a0 + 2) * NCH + c] = acc.z * scale;
    out[(a0 + 3) * NCH + c] = acc.w * scale;
}

extern "C" void kernel_launch(void* const* d_in, const int* in_sizes, int n_in,
                              void* d_out, int out_size) {
    const float* f          = (const float*)d_in[0];
    const float* coords     = (const float*)d_in[1];
    const float* out_coords = (const float*)d_in[2];
    const float* mu         = (const float*)d_in[3];
    const float* r_norms    = (const float*)d_in[4];
    const float* an0        = (const float*)d_in[5];
    const float* an1        = (const float*)d_in[6];
    (void)in_sizes; (void)n_in; (void)out_size;

    dim3 grid(A_TOTAL / BLOCK, NSPLIT);
    svp_main<<<grid, BLOCK>>>(f, coords, out_coords, mu);

    const int total = NCH * (A_TOTAL / 4);   // 32768 threads
    svp_reduce<<<total / 256, 256>>>((float*)d_out, r_norms, an0, an1);
}